// round 10
// baseline (speedup 1.0000x reference)
#include <cuda_runtime.h>
#include <math.h>
#include <stdint.h>

#define DIMF 128
#define N_LEGO 50000
#define N_POINT 100000
#define NE_LL 500000
#define NE_PP 400000
#define NE_LP 500000
#define NE_PL 500000
#define NEG_INF_KEY 0x007FFFFFu
#define SCAN_B 512

// ---------------- scratch ----------------
__device__ float    g_xl[N_LEGO * DIMF];
__device__ float    g_xp[N_POINT * DIMF];
__device__ float    g_la[N_LEGO * DIMF];
__device__ float    g_pa[N_POINT * DIMF];
__device__ float    g_hs[N_POINT * DIMF];
__device__ float    g_ss[N_POINT];
__device__ float    g_sd[N_POINT];
__device__ float    g_escore[NE_LL];
__device__ unsigned g_mkey[N_POINT];
__device__ float    g_dsum[N_POINT];
__device__ float    g_PQ[(size_t)N_POINT * 1024];
__device__ unsigned g_emax[N_POINT * DIMF];
__device__ float    g_WcatT[4 * 128 * 512];
__device__ float    g_bcatT[4 * 512];
__device__ float    g_WcatE[4 * 128 * 1024];
__device__ float    g_wad[DIMF];
// packed bf16 hi/mid weights, [K/2][N] u32
__device__ uint32_t g_WTh[4 * 64 * 512],  g_WTm[4 * 64 * 512];
__device__ uint32_t g_WEh[4 * 64 * 1024], g_WEm[4 * 64 * 1024];
__device__ uint32_t g_W2h[4 * 256 * 128], g_W2m[4 * 256 * 128];
__device__ uint32_t g_Gh[4 * 64 * 128],   g_Gm[4 * 64 * 128];
// sort scratch + sorted edge lists
__device__ int g_hist[N_POINT], g_work[N_POINT], g_bsum[SCAN_B];
__device__ int g_sll_s[NE_LL], g_sll_d[NE_LL];
__device__ int g_spp_s[NE_PP], g_spp_d[NE_PP];
__device__ int g_slp_s[NE_LP], g_slp_d[NE_LP];
__device__ int g_spl_s[NE_PL], g_spl_d[NE_PL];

// ---------------- helpers ----------------
__device__ __forceinline__ unsigned fkey(float f) {
    unsigned u = __float_as_uint(f);
    return (u & 0x80000000u) ? ~u : (u | 0x80000000u);
}
__device__ __forceinline__ float fdecode(unsigned kk) {
    unsigned u = (kk & 0x80000000u) ? (kk ^ 0x80000000u) : ~kk;
    return __uint_as_float(u);
}
__device__ __forceinline__ uint2 bfsplit2(float v0, float v1) {
    uint32_t h, m;
    asm("cvt.rn.bf16x2.f32 %0, %1, %2;" : "=r"(h) : "f"(v1), "f"(v0));
    float h0 = __uint_as_float(h << 16);
    float h1 = __uint_as_float(h & 0xffff0000u);
    asm("cvt.rn.bf16x2.f32 %0, %1, %2;" : "=r"(m) : "f"(v1 - h1), "f"(v0 - h0));
    return make_uint2(h, m);
}
__device__ __forceinline__ void cp_async16(void* dst, const void* src) {
    uint32_t d = (uint32_t)__cvta_generic_to_shared(dst);
    asm volatile("cp.async.ca.shared.global [%0], [%1], 16;\n" :: "r"(d), "l"(src));
}

// ---------------- GEMM tiling ----------------
// BM=128,BN=128,BK=32. 256 thr, 8 warps (4M x 2N), warp 32x64.
// A: split-at-STS double buffer. B: packed gmem -> 3-slot cp.async ring.
#define AHS 20
#define AMO 2560
#define A_ST 5120
#define BHS 136
#define BMO 2176
#define B_SL 4352
#define B_BASE 10240
#define SMEM_BYTES ((B_BASE + 3 * B_SL) * 4)

#define MMA_BF16(accv, a0, a1, a2, a3, b0, b1)                                     \
    asm("mma.sync.aligned.m16n8k16.row.col.f32.bf16.bf16.f32 "                     \
        "{%0,%1,%2,%3}, {%4,%5,%6,%7}, {%8,%9}, {%0,%1,%2,%3};"                    \
        : "+f"(accv[0]), "+f"(accv[1]), "+f"(accv[2]), "+f"(accv[3])               \
        : "r"(a0), "r"(a1), "r"(a2), "r"(a3), "r"(b0), "r"(b1))

#define BF_COMPUTE(sa, sb)                                                         \
    {                                                                              \
        _Pragma("unroll")                                                          \
        for (int kc = 0; kc < 2; kc++) {                                           \
            uint32_t ah[2][4], am[2][4];                                           \
            _Pragma("unroll")                                                      \
            for (int mt = 0; mt < 2; mt++) {                                       \
                int r0 = wm + mt * 16 + g;                                         \
                int o0 = r0 * AHS + kc * 8 + t, o1 = (r0 + 8) * AHS + kc * 8 + t;  \
                ah[mt][0] = (sa)[o0];           ah[mt][1] = (sa)[o1];              \
                ah[mt][2] = (sa)[o0 + 4];       ah[mt][3] = (sa)[o1 + 4];          \
                am[mt][0] = (sa)[AMO + o0];     am[mt][1] = (sa)[AMO + o1];        \
                am[mt][2] = (sa)[AMO + o0 + 4]; am[mt][3] = (sa)[AMO + o1 + 4];    \
            }                                                                      \
            _Pragma("unroll")                                                      \
            for (int nt2 = 0; nt2 < 8; nt2++) {                                    \
                int nn = wn + nt2 * 8 + g;                                         \
                int p0 = (kc * 8 + t) * BHS + nn, p1 = (kc * 8 + t + 4) * BHS + nn;\
                uint32_t b0h = (sb)[p0],       b1h = (sb)[p1];                     \
                uint32_t b0m = (sb)[BMO + p0], b1m = (sb)[BMO + p1];               \
                _Pragma("unroll")                                                  \
                for (int mt = 0; mt < 2; mt++) {                                   \
                    MMA_BF16(acc[mt][nt2], am[mt][0], am[mt][1], am[mt][2],        \
                             am[mt][3], b0h, b1h);                                 \
                    MMA_BF16(acc[mt][nt2], ah[mt][0], ah[mt][1], ah[mt][2],        \
                             ah[mt][3], b0m, b1m);                                 \
                    MMA_BF16(acc[mt][nt2], ah[mt][0], ah[mt][1], ah[mt][2],        \
                             ah[mt][3], b0h, b1h);                                 \
                }                                                                  \
            }                                                                      \
        }                                                                          \
    }

#define STS_A4(sa, row, c4, v4)                                                    \
    {                                                                              \
        int k2c = (c4) >> 1;                                                       \
        uint2 p01 = bfsplit2((v4).x, (v4).y);                                      \
        uint2 p23 = bfsplit2((v4).z, (v4).w);                                      \
        *(uint2*)((sa) + (row) * AHS + k2c) = make_uint2(p01.x, p23.x);            \
        *(uint2*)((sa) + AMO + (row) * AHS + k2c) = make_uint2(p01.y, p23.y);      \
    }

// copy one 32-K packed B tile (hi+mid, 16 k2-rows x 128 cols) into ring slot
#define ISSUE_B(Bh_, Bm_, Nn, nb, kt, slot)                                        \
    {                                                                              \
        uint32_t* sbd = smu + B_BASE + (slot) * B_SL;                              \
        int k2t = (kt) >> 1;                                                       \
        _Pragma("unroll")                                                          \
        for (int ii = 0; ii < 4; ii++) {                                           \
            int cc = tid + ii * 256;                                               \
            int reg = cc >> 9, ci = cc & 511;                                      \
            int row = ci >> 5, off = (ci & 31) * 4;                                \
            const uint32_t* sp = (reg ? (Bm_) : (Bh_)) +                           \
                (size_t)(k2t + row) * (Nn) + (nb) + off;                           \
            cp_async16(sbd + (reg ? BMO : 0) + row * BHS + off, sp);               \
        }                                                                          \
        asm volatile("cp.async.commit_group;\n" ::);                               \
    }

// ---------------- generic GEMM: C = A @ Bpacked (+bias) ----------------
__global__ __launch_bounds__(256, 2) void bf3ps_gemm_kernel(
    const float* __restrict__ A, const uint32_t* __restrict__ Bh,
    const uint32_t* __restrict__ Bm, const float* __restrict__ bias,
    float* __restrict__ C, int M, int N, int K)
{
    extern __shared__ uint32_t smu[];
    const int tid = threadIdx.x;
    const int warp = tid >> 5, lane = tid & 31;
    const int g = lane >> 2, t = lane & 3;
    const int warp_m = warp & 3, warp_n = warp >> 2;
    const int m_base = blockIdx.y * 128, n_base = blockIdx.x * 128;
    const int wm = warp_m * 32, wn = warp_n * 64;
    const int a_row = tid >> 3, a_c4 = (tid & 7) * 4;
    const int nt = K >> 5;

    float acc[2][8][4];
#pragma unroll
    for (int i = 0; i < 2; i++)
#pragma unroll
        for (int j = 0; j < 8; j++)
#pragma unroll
            for (int c = 0; c < 4; c++) acc[i][j][c] = 0.f;

    float4 av[4];
    const float4 f4z = make_float4(0.f, 0.f, 0.f, 0.f);
#define GEN_LDG(kt)                                                                \
    {                                                                              \
        _Pragma("unroll")                                                          \
        for (int ii = 0; ii < 4; ii++) {                                           \
            int row = a_row + ii * 32, gr = m_base + row;                          \
            av[ii] = (gr < M) ? *(const float4*)(A + (size_t)gr * K + (kt) + a_c4) \
                              : f4z;                                               \
        }                                                                          \
    }

    GEN_LDG(0);
    ISSUE_B(Bh, Bm, N, n_base, 0, 0);
    if (nt > 1) ISSUE_B(Bh, Bm, N, n_base, 32, 1);

    for (int i2 = 0; i2 < nt; i2++) {
        uint32_t* sa = smu + (i2 & 1) * A_ST;
#pragma unroll
        for (int ii = 0; ii < 4; ii++) STS_A4(sa, a_row + ii * 32, a_c4, av[ii]);
        if (i2 + 1 < nt) asm volatile("cp.async.wait_group 1;\n" ::);
        else             asm volatile("cp.async.wait_group 0;\n" ::);
        __syncthreads();
        if (i2 + 1 < nt) GEN_LDG((i2 + 1) * 32);
        if (i2 + 2 < nt) ISSUE_B(Bh, Bm, N, n_base, (i2 + 2) * 32, (i2 + 2) % 3);
        BF_COMPUTE(sa, smu + B_BASE + (i2 % 3) * B_SL);
    }

#pragma unroll
    for (int mt = 0; mt < 2; mt++) {
        int r0 = m_base + wm + mt * 16 + g, r1 = r0 + 8;
#pragma unroll
        for (int nt2 = 0; nt2 < 8; nt2++) {
            int c = n_base + wn + nt2 * 8 + 2 * t;
            float b0 = 0.f, b1 = 0.f;
            if (bias) { b0 = bias[c]; b1 = bias[c + 1]; }
            if (r0 < M) *(float2*)(C + (size_t)r0 * N + c) =
                make_float2(acc[mt][nt2][0] + b0, acc[mt][nt2][1] + b1);
            if (r1 < M) *(float2*)(C + (size_t)r1 * N + c) =
                make_float2(acc[mt][nt2][2] + b0, acc[mt][nt2][3] + b1);
        }
    }
}

// ---------------- fused EdgeConv MLP2 + segment-max (packed W2) ----------------
__global__ __launch_bounds__(256, 2) void edge_bf3ps_kernel(
    const float* __restrict__ PQ, const float* __restrict__ b1,
    const uint32_t* __restrict__ W2h, const uint32_t* __restrict__ W2m,
    const int* __restrict__ src, const int* __restrict__ dst,
    unsigned* __restrict__ emax, int E)
{
    extern __shared__ uint32_t smu[];
    __shared__ int se[128], de[128];
    const int tid = threadIdx.x;
    const int warp = tid >> 5, lane = tid & 31;
    const int g = lane >> 2, t = lane & 3;
    const int warp_m = warp & 3, warp_n = warp >> 2;
    const int e_base = blockIdx.y * 128;
    const int wm = warp_m * 32, wn = warp_n * 64;
    const int a_row = tid >> 3, a_c4 = (tid & 7) * 4;

    if (tid < 128) {
        int e = e_base + tid;
        bool ok = (e < E);
        se[tid] = ok ? src[e] : 0;
        de[tid] = ok ? dst[e] : 0;
    }
    __syncthreads();

    float acc[2][8][4];
#pragma unroll
    for (int i = 0; i < 2; i++)
#pragma unroll
        for (int j = 0; j < 8; j++)
#pragma unroll
            for (int c = 0; c < 4; c++) acc[i][j][c] = 0.f;

#define EB_A_STS(kt, sa)                                                           \
    {                                                                              \
        float4 bb = *(const float4*)(b1 + (kt) + a_c4);                            \
        _Pragma("unroll")                                                          \
        for (int ii = 0; ii < 4; ii++) {                                           \
            int row = a_row + ii * 32;                                             \
            size_t dof = (size_t)de[row] * 1024, sof = (size_t)se[row] * 1024 + 512; \
            float4 rv = *(const float4*)(PQ + dof + (kt) + a_c4);                  \
            float4 qv = *(const float4*)(PQ + sof + (kt) + a_c4);                  \
            float4 h;                                                              \
            h.x = fmaxf(rv.x + qv.x + bb.x, 0.f);                                  \
            h.y = fmaxf(rv.y + qv.y + bb.y, 0.f);                                  \
            h.z = fmaxf(rv.z + qv.z + bb.z, 0.f);                                  \
            h.w = fmaxf(rv.w + qv.w + bb.w, 0.f);                                  \
            STS_A4(sa, row, a_c4, h);                                              \
        }                                                                          \
    }

    EB_A_STS(0, smu);
    ISSUE_B(W2h, W2m, 128, 0, 0, 0);
    ISSUE_B(W2h, W2m, 128, 0, 32, 1);

    const int nt = 16;   // K = 512
    for (int i2 = 0; i2 < nt; i2++) {
        if (i2 + 1 < nt) asm volatile("cp.async.wait_group 1;\n" ::);
        else             asm volatile("cp.async.wait_group 0;\n" ::);
        __syncthreads();
        if (i2 + 2 < nt) ISSUE_B(W2h, W2m, 128, 0, (i2 + 2) * 32, (i2 + 2) % 3);
        BF_COMPUTE(smu + (i2 & 1) * A_ST, smu + B_BASE + (i2 % 3) * B_SL);
        if (i2 + 1 < nt) EB_A_STS((i2 + 1) * 32, smu + ((i2 + 1) & 1) * A_ST);
    }

#pragma unroll
    for (int mt = 0; mt < 2; mt++) {
        int r0 = wm + mt * 16 + g, r1 = r0 + 8;
        int e0 = e_base + r0, e1 = e_base + r1;
        int d0 = de[r0], d1 = de[r1];
#pragma unroll
        for (int nt2 = 0; nt2 < 8; nt2++) {
            int c = wn + nt2 * 8 + 2 * t;
            if (e0 < E) {
                atomicMax(emax + (size_t)d0 * DIMF + c,     fkey(acc[mt][nt2][0]));
                atomicMax(emax + (size_t)d0 * DIMF + c + 1, fkey(acc[mt][nt2][1]));
            }
            if (e1 < E) {
                atomicMax(emax + (size_t)d1 * DIMF + c,     fkey(acc[mt][nt2][2]));
                atomicMax(emax + (size_t)d1 * DIMF + c + 1, fkey(acc[mt][nt2][3]));
            }
        }
    }
}

// ---------------- one-time weight prep ----------------
__global__ void concat_trans_kernel(const float* Wq, const float* Wk, const float* Wv,
                                    const float* Ws, const float* bq, const float* bk,
                                    const float* bv, const float* bs,
                                    float* Wcat, float* bcat)
{
    int i = blockIdx.x * blockDim.x + threadIdx.x;
    if (i >= 4 * 128 * 512) return;
    int inst = i >> 16, r = (i >> 9) & 127, j = i & 511;
    int sel = j >> 7, jj = j & 127;
    const float* W = sel == 0 ? Wq : sel == 1 ? Wk : sel == 2 ? Wv : Ws;
    Wcat[i] = W[((size_t)inst * 128 + r) * 128 + jj];
    if (r == 0) {
        const float* bb = sel == 0 ? bq : sel == 1 ? bk : sel == 2 ? bv : bs;
        bcat[inst * 512 + j] = bb[inst * 128 + jj];
    }
}
__global__ void concat_edge_kernel(const float* W1, float* Wcat)
{
    int i = blockIdx.x * blockDim.x + threadIdx.x;
    if (i >= 4 * 128 * 1024) return;
    int inst = i >> 17, r = (i >> 10) & 127, j = i & 1023;
    const float* Wi = W1 + (size_t)inst * 256 * 512;
    if (j < 512) Wcat[i] = Wi[(size_t)r * 512 + j] - Wi[(size_t)(128 + r) * 512 + j];
    else         Wcat[i] = Wi[(size_t)(128 + r) * 512 + (j - 512)];
}
// pack fp32 [K][N] -> hi/mid [K/2][N]
__global__ void pack_kernel(const float* __restrict__ W, uint32_t* __restrict__ Wh,
                            uint32_t* __restrict__ Wm, int K2, int N)
{
    int i = blockIdx.x * blockDim.x + threadIdx.x;
    if (i >= K2 * N) return;
    int k2 = i / N, n = i % N;
    uint2 p = bfsplit2(W[(size_t)(2 * k2) * N + n], W[(size_t)(2 * k2 + 1) * N + n]);
    Wh[i] = p.x; Wm[i] = p.y;
}
__global__ void wad_kernel(const float* __restrict__ W, const float* __restrict__ ad,
                           float* __restrict__ wad)
{
    int j = threadIdx.x;
    float s = 0.f;
    for (int kk = 0; kk < 128; kk++) s += W[j * 128 + kk] * ad[kk];
    wad[j] = s;
}

// ---------------- counting sort by dst ----------------
__global__ void fill_i32_kernel(int* p, int val, int n) {
    int i = blockIdx.x * blockDim.x + threadIdx.x;
    if (i < n) p[i] = val;
}
__global__ void count_kernel(const int* __restrict__ dst, int* __restrict__ hist, int E) {
    int e = blockIdx.x * blockDim.x + threadIdx.x;
    if (e < E) atomicAdd(hist + dst[e], 1);
}
__global__ void scan1_kernel(const int* __restrict__ hist, int* __restrict__ off,
                             int* __restrict__ bsum, int n) {
    __shared__ int sh[SCAN_B];
    int tid = threadIdx.x, i = blockIdx.x * SCAN_B + tid;
    int v = (i < n) ? hist[i] : 0;
    sh[tid] = v; __syncthreads();
    for (int d = 1; d < SCAN_B; d <<= 1) {
        int t2 = (tid >= d) ? sh[tid - d] : 0;
        __syncthreads(); sh[tid] += t2; __syncthreads();
    }
    if (i < n) off[i] = sh[tid] - v;
    if (tid == SCAN_B - 1) bsum[blockIdx.x] = sh[tid];
}
__global__ void scan2_kernel(int* __restrict__ bsum, int nb) {
    __shared__ int sh[SCAN_B];
    int tid = threadIdx.x;
    int v = (tid < nb) ? bsum[tid] : 0;
    sh[tid] = v; __syncthreads();
    for (int d = 1; d < SCAN_B; d <<= 1) {
        int t2 = (tid >= d) ? sh[tid - d] : 0;
        __syncthreads(); sh[tid] += t2; __syncthreads();
    }
    if (tid < nb) bsum[tid] = sh[tid] - v;
}
__global__ void scan3_kernel(const int* __restrict__ off, const int* __restrict__ bsum,
                             int* __restrict__ work, int n) {
    int i = blockIdx.x * blockDim.x + threadIdx.x;
    if (i < n) work[i] = off[i] + bsum[i / SCAN_B];
}
__global__ void scatter_kernel(const int* __restrict__ src, const int* __restrict__ dst,
                               int* __restrict__ work,
                               int* __restrict__ osrc, int* __restrict__ odst, int E) {
    int e = blockIdx.x * blockDim.x + threadIdx.x;
    if (e >= E) return;
    int d = dst[e];
    int pos = atomicAdd(work + d, 1);
    osrc[pos] = src[e];
    odst[pos] = d;
}

// ---------------- graph kernels ----------------
__global__ void reset_softmax_kernel(unsigned* mkey, float* dsum, int n) {
    int i = blockIdx.x * blockDim.x + threadIdx.x;
    if (i < n) { mkey[i] = NEG_INF_KEY; dsum[i] = 0.f; }
}
__global__ void fill_u32_kernel(unsigned* p, unsigned val, int n) {
    int i = blockIdx.x * blockDim.x + threadIdx.x;
    if (i < n) p[i] = val;
}
__global__ void copy_skip_kernel(const float* __restrict__ qkvs, float* __restrict__ out, int n) {
    int i = blockIdx.x * blockDim.x + threadIdx.x;
    if (i >= n * 32) return;
    int row = i >> 5, f = (i & 31) * 4;
    *(float4*)(out + (size_t)row * DIMF + f) =
        *(const float4*)(qkvs + (size_t)row * 512 + 384 + f);
}
__global__ void trans_score_kernel(
    const float* __restrict__ qkvs,
    const int* __restrict__ src, const int* __restrict__ dst,
    float* __restrict__ score, unsigned* __restrict__ mkey, int E, float scale)
{
    int idx = blockIdx.x * blockDim.x + threadIdx.x;
    int e = idx >> 5, lane = idx & 31;
    if (e >= E) return;
    int d = dst[e], s0 = src[e];
    float4 qv = *(const float4*)(qkvs + (size_t)d * 512 + lane * 4);
    float4 kv = *(const float4*)(qkvs + (size_t)s0 * 512 + 128 + lane * 4);
    float s = qv.x * kv.x + qv.y * kv.y + qv.z * kv.z + qv.w * kv.w;
#pragma unroll
    for (int o = 16; o; o >>= 1) s += __shfl_xor_sync(0xffffffffu, s, o);
    if (lane == 0) {
        s *= scale;
        score[e] = s;
        atomicMax(mkey + d, fkey(s));
    }
}
__global__ void node_dot_kernel(const float* __restrict__ h, const float* __restrict__ avec,
                                float* __restrict__ out, int n)
{
    int idx = blockIdx.x * blockDim.x + threadIdx.x;
    int i = idx >> 5, lane = idx & 31;
    if (i >= n) return;
    float4 hv = *(const float4*)(h + (size_t)i * DIMF + lane * 4);
    float4 av = *(const float4*)(avec + lane * 4);
    float s = hv.x * av.x + hv.y * av.y + hv.z * av.z + hv.w * av.w;
#pragma unroll
    for (int o = 16; o; o >>= 1) s += __shfl_xor_sync(0xffffffffu, s, o);
    if (lane == 0) out[i] = s;
}
__global__ void gat_score_kernel(const float* __restrict__ ss, const float* __restrict__ sd,
                                 const int* __restrict__ src, const int* __restrict__ dst,
                                 float* __restrict__ score, unsigned* __restrict__ mkey, int E)
{
    int e = blockIdx.x * blockDim.x + threadIdx.x;
    if (e >= E) return;
    float s = ss[src[e]] + sd[dst[e]];
    s = (s > 0.f) ? s : 0.2f * s;
    score[e] = s;
    atomicMax(mkey + dst[e], fkey(s));
}
__global__ void expsum_kernel(float* __restrict__ score, const unsigned* __restrict__ mkey,
                              float* __restrict__ dsum, const int* __restrict__ dst, int E)
{
    int e = blockIdx.x * blockDim.x + threadIdx.x;
    if (e >= E) return;
    int d = dst[e];
    float m = fdecode(mkey[d]);
    if (!isfinite(m)) m = 0.f;
    float ex = expf(score[e] - m);
    score[e] = ex;
    atomicAdd(dsum + d, ex);
}
__global__ void aggregate_kernel(const float* __restrict__ score, const float* __restrict__ dsum,
                                 const float* __restrict__ v, int vstride,
                                 const int* __restrict__ src, const int* __restrict__ dst,
                                 float* __restrict__ out, int E)
{
    int idx = blockIdx.x * blockDim.x + threadIdx.x;
    int e = idx >> 5, lane = idx & 31;
    if (e >= E) return;
    int d = dst[e], s0 = src[e];
    float w = score[e] / (dsum[d] + 1e-16f);
    float4 vv = *(const float4*)(v + (size_t)s0 * vstride + lane * 4);
    float* op = out + (size_t)d * DIMF + lane * 4;
    asm volatile("red.global.add.v4.f32 [%0], {%1, %2, %3, %4};"
                 :: "l"(op), "f"(w * vv.x), "f"(w * vv.y), "f"(w * vv.z), "f"(w * vv.w)
                 : "memory");
}
__global__ void bias_add_kernel(float* __restrict__ out, const float* __restrict__ b, int n) {
    int i = blockIdx.x * blockDim.x + threadIdx.x;
    if (i >= n * 32) return;
    int f = (i & 31) * 4;
    float4 bv = *(const float4*)(b + f);
    float4 ov = *(float4*)(out + (size_t)i * 4);
    ov.x += bv.x; ov.y += bv.y; ov.z += bv.z; ov.w += bv.w;
    *(float4*)(out + (size_t)i * 4) = ov;
}
__global__ void finalize_max_b2_kernel(const unsigned* __restrict__ emax,
                                       const float* __restrict__ b2,
                                       float* __restrict__ out, int total) {
    int i = blockIdx.x * blockDim.x + threadIdx.x;
    if (i >= total) return;
    float v = fdecode(emax[i]);
    out[i] = isfinite(v) ? v + b2[i & (DIMF - 1)] : 0.f;
}

// ---------------- host orchestration ----------------
static inline int div_up(int a, int b) { return (a + b - 1) / b; }

struct Scratch {
    float *xl, *xp, *la, *pa, *hs, *ss, *sd, *escore, *dsum, *PQ, *WcatT, *bcatT, *WcatE, *wad;
    uint32_t *WTh, *WTm, *WEh, *WEm, *W2h, *W2m, *Gh, *Gm;
    unsigned *mkey, *emax;
    int *hist, *work, *bsum;
    int *sll_s, *sll_d, *spp_s, *spp_d, *slp_s, *slp_d, *spl_s, *spl_d;
};

static void sort_graph(const Scratch& S, const int* src, const int* dst, int E, int n,
                       int* osrc, int* odst)
{
    fill_i32_kernel<<<div_up(n, 256), 256>>>(S.hist, 0, n);
    count_kernel<<<div_up(E, 256), 256>>>(dst, S.hist, E);
    int nb = div_up(n, SCAN_B);
    scan1_kernel<<<nb, SCAN_B>>>(S.hist, S.work, S.bsum, n);
    scan2_kernel<<<1, SCAN_B>>>(S.bsum, nb);
    scan3_kernel<<<div_up(n, 256), 256>>>(S.work, S.bsum, S.hist, n);
    scatter_kernel<<<div_up(E, 256), 256>>>(src, dst, S.hist, osrc, odst, E);
}

static void gemm_ps(const float* A, const uint32_t* Bh, const uint32_t* Bm,
                    const float* bias, float* C, int M, int N, int K) {
    dim3 grid(N / 128, div_up(M, 128));
    bf3ps_gemm_kernel<<<grid, 256, SMEM_BYTES>>>(A, Bh, Bm, bias, C, M, N, K);
}

static void run_trans(const Scratch& S, const float* x, int n, int inst,
                      const int* src, const int* dst, int E, float* out)
{
    gemm_ps(x, S.WTh + (size_t)inst * 64 * 512, S.WTm + (size_t)inst * 64 * 512,
            S.bcatT + inst * 512, S.PQ, n, 512, DIMF);
    copy_skip_kernel<<<div_up(n * 32, 256), 256>>>(S.PQ, out, n);
    reset_softmax_kernel<<<div_up(n, 256), 256>>>(S.mkey, S.dsum, n);
    float scale = 1.f / sqrtf((float)DIMF);
    trans_score_kernel<<<div_up(E * 32, 256), 256>>>(S.PQ, src, dst, S.escore, S.mkey, E, scale);
    expsum_kernel<<<div_up(E, 256), 256>>>(S.escore, S.mkey, S.dsum, dst, E);
    aggregate_kernel<<<div_up(E * 32, 256), 256>>>(S.escore, S.dsum, S.PQ + 256, 512,
                                                   src, dst, out, E);
}

static void run_gat(const Scratch& S, const float* xs, int ns, const float* xd, int nd,
                    const int* src, const int* dst, int E, int inst,
                    const float* W, const float* a_src, const float* a_dst, const float* b,
                    float* out)
{
    gemm_ps(xs, S.Gh + (size_t)inst * 64 * 128, S.Gm + (size_t)inst * 64 * 128,
            nullptr, S.hs, ns, DIMF, DIMF);
    wad_kernel<<<1, 128>>>(W, a_dst, S.wad);
    node_dot_kernel<<<div_up(ns * 32, 256), 256>>>(S.hs, a_src, S.ss, ns);
    node_dot_kernel<<<div_up(nd * 32, 256), 256>>>(xd, S.wad, S.sd, nd);
    reset_softmax_kernel<<<div_up(nd, 256), 256>>>(S.mkey, S.dsum, nd);
    gat_score_kernel<<<div_up(E, 256), 256>>>(S.ss, S.sd, src, dst, S.escore, S.mkey, E);
    expsum_kernel<<<div_up(E, 256), 256>>>(S.escore, S.mkey, S.dsum, dst, E);
    aggregate_kernel<<<div_up(E * 32, 256), 256>>>(S.escore, S.dsum, S.hs, DIMF,
                                                   src, dst, out, E);
    bias_add_kernel<<<div_up(nd * 32, 256), 256>>>(out, b, nd);
}

static void run_edge(const Scratch& S, const float* x, int n, int inst,
                     const int* src, const int* dst, int E,
                     const float* b1, const float* b2, float* out)
{
    gemm_ps(x, S.WEh + (size_t)inst * 64 * 1024, S.WEm + (size_t)inst * 64 * 1024,
            nullptr, S.PQ, n, 1024, DIMF);
    fill_u32_kernel<<<div_up(n * DIMF, 256), 256>>>(S.emax, NEG_INF_KEY, n * DIMF);
    dim3 grid(1, div_up(E, 128));
    edge_bf3ps_kernel<<<grid, 256, SMEM_BYTES>>>(S.PQ, b1,
                                                 S.W2h + (size_t)inst * 256 * 128,
                                                 S.W2m + (size_t)inst * 256 * 128,
                                                 src, dst, S.emax, E);
    finalize_max_b2_kernel<<<div_up(n * DIMF, 256), 256>>>(S.emax, b2, out, n * DIMF);
}

extern "C" void kernel_launch(void* const* d_in, const int* in_sizes, int n_in,
                              void* d_out, int out_size)
{
    const float* x_lego  = (const float*)d_in[0];
    const float* x_point = (const float*)d_in[1];
    const float* tWq = (const float*)d_in[2];
    const float* tbq = (const float*)d_in[3];
    const float* tWk = (const float*)d_in[4];
    const float* tbk = (const float*)d_in[5];
    const float* tWv = (const float*)d_in[6];
    const float* tbv = (const float*)d_in[7];
    const float* tWs = (const float*)d_in[8];
    const float* tbs = (const float*)d_in[9];
    const float* eW1 = (const float*)d_in[10];
    const float* eb1 = (const float*)d_in[11];
    const float* eW2 = (const float*)d_in[12];
    const float* eb2 = (const float*)d_in[13];
    const float* gW  = (const float*)d_in[14];
    const float* gAs = (const float*)d_in[15];
    const float* gAd = (const float*)d_in[16];
    const float* gb  = (const float*)d_in[17];
    const int* ll_src = (const int*)d_in[18];
    const int* ll_dst = (const int*)d_in[19];
    const int* pp_src = (const int*)d_in[20];
    const int* pp_dst = (const int*)d_in[21];
    const int* lp_src = (const int*)d_in[22];
    const int* lp_dst = (const int*)d_in[23];
    const int* pl_src = (const int*)d_in[24];
    const int* pl_dst = (const int*)d_in[25];

    cudaFuncSetAttribute(bf3ps_gemm_kernel, cudaFuncAttributeMaxDynamicSharedMemorySize,
                         SMEM_BYTES);
    cudaFuncSetAttribute(edge_bf3ps_kernel, cudaFuncAttributeMaxDynamicSharedMemorySize,
                         SMEM_BYTES);

    Scratch S;
    cudaGetSymbolAddress((void**)&S.xl, g_xl);
    cudaGetSymbolAddress((void**)&S.xp, g_xp);
    cudaGetSymbolAddress((void**)&S.la, g_la);
    cudaGetSymbolAddress((void**)&S.pa, g_pa);
    cudaGetSymbolAddress((void**)&S.hs, g_hs);
    cudaGetSymbolAddress((void**)&S.ss, g_ss);
    cudaGetSymbolAddress((void**)&S.sd, g_sd);
    cudaGetSymbolAddress((void**)&S.escore, g_escore);
    cudaGetSymbolAddress((void**)&S.dsum, g_dsum);
    cudaGetSymbolAddress((void**)&S.PQ, g_PQ);
    cudaGetSymbolAddress((void**)&S.mkey, g_mkey);
    cudaGetSymbolAddress((void**)&S.emax, g_emax);
    cudaGetSymbolAddress((void**)&S.WcatT, g_WcatT);
    cudaGetSymbolAddress((void**)&S.bcatT, g_bcatT);
    cudaGetSymbolAddress((void**)&S.WcatE, g_WcatE);
    cudaGetSymbolAddress((void**)&S.wad, g_wad);
    cudaGetSymbolAddress((void**)&S.WTh, g_WTh);
    cudaGetSymbolAddress((void**)&S.WTm, g_WTm);
    cudaGetSymbolAddress((void**)&S.WEh, g_WEh);
    cudaGetSymbolAddress((void**)&S.WEm, g_WEm);
    cudaGetSymbolAddress((void**)&S.W2h, g_W2h);
    cudaGetSymbolAddress((void**)&S.W2m, g_W2m);
    cudaGetSymbolAddress((void**)&S.Gh, g_Gh);
    cudaGetSymbolAddress((void**)&S.Gm, g_Gm);
    cudaGetSymbolAddress((void**)&S.hist, g_hist);
    cudaGetSymbolAddress((void**)&S.work, g_work);
    cudaGetSymbolAddress((void**)&S.bsum, g_bsum);
    cudaGetSymbolAddress((void**)&S.sll_s, g_sll_s);
    cudaGetSymbolAddress((void**)&S.sll_d, g_sll_d);
    cudaGetSymbolAddress((void**)&S.spp_s, g_spp_s);
    cudaGetSymbolAddress((void**)&S.spp_d, g_spp_d);
    cudaGetSymbolAddress((void**)&S.slp_s, g_slp_s);
    cudaGetSymbolAddress((void**)&S.slp_d, g_slp_d);
    cudaGetSymbolAddress((void**)&S.spl_s, g_spl_s);
    cudaGetSymbolAddress((void**)&S.spl_d, g_spl_d);

    cudaMemcpyAsync(S.xl, x_lego,  (size_t)N_LEGO * DIMF * sizeof(float),  cudaMemcpyDeviceToDevice);
    cudaMemcpyAsync(S.xp, x_point, (size_t)N_POINT * DIMF * sizeof(float), cudaMemcpyDeviceToDevice);

    // one-time: concats, packs, sorts
    concat_trans_kernel<<<div_up(4 * 128 * 512, 256), 256>>>(tWq, tWk, tWv, tWs,
                                                             tbq, tbk, tbv, tbs,
                                                             S.WcatT, S.bcatT);
    concat_edge_kernel<<<div_up(4 * 128 * 1024, 256), 256>>>(eW1, S.WcatE);
    for (int inst = 0; inst < 4; inst++) {
        pack_kernel<<<div_up(64 * 512, 256), 256>>>(
            S.WcatT + (size_t)inst * 128 * 512,
            S.WTh + (size_t)inst * 64 * 512, S.WTm + (size_t)inst * 64 * 512, 64, 512);
        pack_kernel<<<div_up(64 * 1024, 256), 256>>>(
            S.WcatE + (size_t)inst * 128 * 1024,
            S.WEh + (size_t)inst * 64 * 1024, S.WEm + (size_t)inst * 64 * 1024, 64, 1024);
        pack_kernel<<<div_up(256 * 128, 256), 256>>>(
            eW2 + (size_t)inst * 512 * 128,
            S.W2h + (size_t)inst * 256 * 128, S.W2m + (size_t)inst * 256 * 128, 256, 128);
        pack_kernel<<<div_up(64 * 128, 256), 256>>>(
            gW + (size_t)inst * 128 * 128,
            S.Gh + (size_t)inst * 64 * 128, S.Gm + (size_t)inst * 64 * 128, 64, 128);
    }
    sort_graph(S, ll_src, ll_dst, NE_LL, N_LEGO,  S.sll_s, S.sll_d);
    sort_graph(S, pp_src, pp_dst, NE_PP, N_POINT, S.spp_s, S.spp_d);
    sort_graph(S, lp_src, lp_dst, NE_LP, N_POINT, S.slp_s, S.slp_d);
    sort_graph(S, pl_src, pl_dst, NE_PL, N_LEGO,  S.spl_s, S.spl_d);

    for (int layer = 0; layer < 2; layer++) {
        int iA = 2 * layer, iB = 2 * layer + 1;
        int i_lp = 2 * layer, i_pl = 2 * layer + 1;

        run_trans(S, S.xl, N_LEGO, iA, S.sll_s, S.sll_d, NE_LL, S.la);
        run_gat(S, S.xp, N_POINT, S.xl, N_LEGO, S.spl_s, S.spl_d, NE_PL, i_pl,
                gW + i_pl * DIMF * DIMF, gAs + i_pl * DIMF, gAd + i_pl * DIMF, gb + i_pl * DIMF,
                S.la);

        run_edge(S, S.xp, N_POINT, iA, S.spp_s, S.spp_d, NE_PP,
                 eb1 + iA * 512, eb2 + iA * DIMF, S.pa);
        run_gat(S, S.xl, N_LEGO, S.xp, N_POINT, S.slp_s, S.slp_d, NE_LP, i_lp,
                gW + i_lp * DIMF * DIMF, gAs + i_lp * DIMF, gAd + i_lp * DIMF, gb + i_lp * DIMF,
                S.pa);

        run_trans(S, S.la, N_LEGO, iB, S.sll_s, S.sll_d, NE_LL, S.xl);
        run_edge(S, S.pa, N_POINT, iB, S.spp_s, S.spp_d, NE_PP,
                 eb1 + iB * 512, eb2 + iB * DIMF, S.xp);
    }

    float* out = (float*)d_out;
    cudaMemcpyAsync(out, S.xl, (size_t)N_LEGO * DIMF * sizeof(float), cudaMemcpyDeviceToDevice);
    cudaMemcpyAsync(out + (size_t)N_LEGO * DIMF, S.xp, (size_t)N_POINT * DIMF * sizeof(float),
                    cudaMemcpyDeviceToDevice);
}

// round 12
// speedup vs baseline: 1.0957x; 1.0957x over previous
#include <cuda_runtime.h>
#include <math.h>
#include <stdint.h>

#define DIMF 128
#define N_LEGO 50000
#define N_POINT 100000
#define NE_LL 500000
#define NE_PP 400000
#define NE_LP 500000
#define NE_PL 500000
#define NEG_INF_KEY 0x007FFFFFu
#define SCAN_B 512

// ---------------- scratch ----------------
__device__ float    g_xl[N_LEGO * DIMF];
__device__ float    g_xp[N_POINT * DIMF];
__device__ float    g_la[N_LEGO * DIMF];
__device__ float    g_pa[N_POINT * DIMF];
__device__ float    g_hs[N_POINT * DIMF];
__device__ float    g_ss[N_POINT];
__device__ float    g_sd[N_POINT];
__device__ float    g_escore[NE_LL];
__device__ float    g_dsum[N_POINT];
__device__ float    g_PQ[(size_t)N_POINT * 1024];
__device__ unsigned g_emax[N_POINT * DIMF];
__device__ float    g_WcatT[4 * 128 * 512];
__device__ float    g_bcatT[4 * 512];
__device__ float    g_WcatE[4 * 128 * 1024];
__device__ float    g_wad[DIMF];
// sort scratch + sorted edge lists + CSR rowptrs
__device__ int g_hist[N_POINT], g_work[N_POINT], g_bsum[SCAN_B];
__device__ int g_sll_s[NE_LL];
__device__ int g_spp_s[NE_PP], g_spp_d[NE_PP];
__device__ int g_slp_s[NE_LP];
__device__ int g_spl_s[NE_PL];
__device__ int g_rp_ll[N_LEGO + 1], g_rp_lp[N_POINT + 1], g_rp_pl[N_LEGO + 1];

// ---------------- helpers ----------------
__device__ __forceinline__ unsigned fkey(float f) {
    unsigned u = __float_as_uint(f);
    return (u & 0x80000000u) ? ~u : (u | 0x80000000u);
}
__device__ __forceinline__ float fdecode(unsigned kk) {
    unsigned u = (kk & 0x80000000u) ? (kk ^ 0x80000000u) : ~kk;
    return __uint_as_float(u);
}
__device__ __forceinline__ uint2 bfsplit2(float v0, float v1) {
    uint32_t h, m;
    asm("cvt.rn.bf16x2.f32 %0, %1, %2;" : "=r"(h) : "f"(v1), "f"(v0));
    float h0 = __uint_as_float(h << 16);
    float h1 = __uint_as_float(h & 0xffff0000u);
    asm("cvt.rn.bf16x2.f32 %0, %1, %2;" : "=r"(m) : "f"(v1 - h1), "f"(v0 - h0));
    return make_uint2(h, m);
}

// ---------------- GEMM (round-7/8 WIN, unchanged) ----------------
#define AHS 20
#define BHS 136
#define AH_OFF 0
#define AM_OFF 2560
#define BH_OFF 5120
#define BM_OFF 7296
#define STAGE_U 9472
#define SMEM_BYTES (2 * STAGE_U * 4)

#define MMA_BF16(accv, a0, a1, a2, a3, b0, b1)                                     \
    asm("mma.sync.aligned.m16n8k16.row.col.f32.bf16.bf16.f32 "                     \
        "{%0,%1,%2,%3}, {%4,%5,%6,%7}, {%8,%9}, {%0,%1,%2,%3};"                    \
        : "+f"(accv[0]), "+f"(accv[1]), "+f"(accv[2]), "+f"(accv[3])               \
        : "r"(a0), "r"(a1), "r"(a2), "r"(a3), "r"(b0), "r"(b1))

#define BF_COMPUTE(sb)                                                             \
    {                                                                              \
        _Pragma("unroll")                                                          \
        for (int kc = 0; kc < 2; kc++) {                                           \
            uint32_t ah[2][4], am[2][4];                                           \
            _Pragma("unroll")                                                      \
            for (int mt = 0; mt < 2; mt++) {                                       \
                int r0 = wm + mt * 16 + g;                                         \
                int o0 = r0 * AHS + kc * 8 + t, o1 = (r0 + 8) * AHS + kc * 8 + t;  \
                ah[mt][0] = (sb)[AH_OFF + o0];     ah[mt][1] = (sb)[AH_OFF + o1];  \
                ah[mt][2] = (sb)[AH_OFF + o0 + 4]; ah[mt][3] = (sb)[AH_OFF + o1 + 4]; \
                am[mt][0] = (sb)[AM_OFF + o0];     am[mt][1] = (sb)[AM_OFF + o1];  \
                am[mt][2] = (sb)[AM_OFF + o0 + 4]; am[mt][3] = (sb)[AM_OFF + o1 + 4]; \
            }                                                                      \
            _Pragma("unroll")                                                      \
            for (int nt = 0; nt < 8; nt++) {                                       \
                int nn = wn + nt * 8 + g;                                          \
                int p0 = (kc * 8 + t) * BHS + nn, p1 = (kc * 8 + t + 4) * BHS + nn;\
                uint32_t b0h = (sb)[BH_OFF + p0], b1h = (sb)[BH_OFF + p1];         \
                uint32_t b0m = (sb)[BM_OFF + p0], b1m = (sb)[BM_OFF + p1];         \
                _Pragma("unroll")                                                  \
                for (int mt = 0; mt < 2; mt++) {                                   \
                    MMA_BF16(acc[mt][nt], am[mt][0], am[mt][1], am[mt][2],         \
                             am[mt][3], b0h, b1h);                                 \
                    MMA_BF16(acc[mt][nt], ah[mt][0], ah[mt][1], ah[mt][2],         \
                             ah[mt][3], b0m, b1m);                                 \
                    MMA_BF16(acc[mt][nt], ah[mt][0], ah[mt][1], ah[mt][2],         \
                             ah[mt][3], b0h, b1h);                                 \
                }                                                                  \
            }                                                                      \
        }                                                                          \
    }

#define STS_A4(sb, row, c4, v4)                                                    \
    {                                                                              \
        int k2c = (c4) >> 1;                                                       \
        uint2 p01 = bfsplit2((v4).x, (v4).y);                                      \
        uint2 p23 = bfsplit2((v4).z, (v4).w);                                      \
        *(uint2*)((sb) + AH_OFF + (row) * AHS + k2c) = make_uint2(p01.x, p23.x);   \
        *(uint2*)((sb) + AM_OFF + (row) * AHS + k2c) = make_uint2(p01.y, p23.y);   \
    }
#define STS_B4(sb, k2, c4, v0, v1)                                                 \
    {                                                                              \
        uint2 q0 = bfsplit2((v0).x, (v1).x);                                       \
        uint2 q1 = bfsplit2((v0).y, (v1).y);                                       \
        uint2 q2 = bfsplit2((v0).z, (v1).z);                                       \
        uint2 q3 = bfsplit2((v0).w, (v1).w);                                       \
        *(uint4*)((sb) + BH_OFF + (k2) * BHS + (c4)) = make_uint4(q0.x, q1.x, q2.x, q3.x); \
        *(uint4*)((sb) + BM_OFF + (k2) * BHS + (c4)) = make_uint4(q0.y, q1.y, q2.y, q3.y); \
    }

__global__ __launch_bounds__(256, 2) void bf3_gemm_kernel(
    const float* __restrict__ A, const float* __restrict__ B,
    const float* __restrict__ bias, float* __restrict__ C,
    int M, int N, int K)
{
    extern __shared__ uint32_t smu[];
    const int tid = threadIdx.x;
    const int warp = tid >> 5, lane = tid & 31;
    const int g = lane >> 2, t = lane & 3;
    const int warp_m = warp & 3, warp_n = warp >> 2;
    const int m_base = blockIdx.y * 128, n_base = blockIdx.x * 128;
    const int wm = warp_m * 32, wn = warp_n * 64;
    const int a_row = tid >> 3, a_c4 = (tid & 7) * 4;
    const int b_k2 = tid >> 5, b_c4 = (tid & 31) * 4;

    float acc[2][8][4];
#pragma unroll
    for (int i = 0; i < 2; i++)
#pragma unroll
        for (int j = 0; j < 8; j++)
#pragma unroll
            for (int c = 0; c < 4; c++) acc[i][j][c] = 0.f;

    float4 av[4], bv0[2], bv1[2];
    const float4 f4z = make_float4(0.f, 0.f, 0.f, 0.f);

#define GEN_LDG(kt)                                                                \
    {                                                                              \
        _Pragma("unroll")                                                          \
        for (int i = 0; i < 4; i++) {                                              \
            int row = a_row + i * 32, gr = m_base + row;                           \
            av[i] = (gr < M) ? *(const float4*)(A + (size_t)gr * K + (kt) + a_c4)  \
                             : f4z;                                                \
        }                                                                          \
        _Pragma("unroll")                                                          \
        for (int i = 0; i < 2; i++) {                                              \
            int k2 = b_k2 + i * 8;                                                 \
            bv0[i] = *(const float4*)(B + (size_t)((kt) + 2 * k2) * N + n_base + b_c4);     \
            bv1[i] = *(const float4*)(B + (size_t)((kt) + 2 * k2 + 1) * N + n_base + b_c4); \
        }                                                                          \
    }
#define GEN_STS(st)                                                                \
    {                                                                              \
        uint32_t* sb = smu + (st) * STAGE_U;                                       \
        _Pragma("unroll")                                                          \
        for (int i = 0; i < 4; i++) STS_A4(sb, a_row + i * 32, a_c4, av[i]);       \
        _Pragma("unroll")                                                          \
        for (int i = 0; i < 2; i++) STS_B4(sb, b_k2 + i * 8, b_c4, bv0[i], bv1[i]);\
    }

    GEN_LDG(0);
    int stage = 0;
    for (int kt = 0; kt < K; kt += 32, stage ^= 1) {
        GEN_STS(stage);
        __syncthreads();
        if (kt + 32 < K) GEN_LDG(kt + 32);
        const uint32_t* sb = smu + stage * STAGE_U;
        BF_COMPUTE(sb);
    }

#pragma unroll
    for (int mt = 0; mt < 2; mt++) {
        int r0 = m_base + wm + mt * 16 + g, r1 = r0 + 8;
#pragma unroll
        for (int nt = 0; nt < 8; nt++) {
            int c = n_base + wn + nt * 8 + 2 * t;
            float b0 = 0.f, b1 = 0.f;
            if (bias) { b0 = bias[c]; b1 = bias[c + 1]; }
            if (r0 < M) *(float2*)(C + (size_t)r0 * N + c) =
                make_float2(acc[mt][nt][0] + b0, acc[mt][nt][1] + b1);
            if (r1 < M) *(float2*)(C + (size_t)r1 * N + c) =
                make_float2(acc[mt][nt][2] + b0, acc[mt][nt][3] + b1);
        }
    }
}

// ---------------- fused EdgeConv MLP2 + segment-max (round-8 WIN, unchanged) ----------------
__global__ __launch_bounds__(256, 2) void edge_bf3_kernel(
    const float* __restrict__ PQ, const float* __restrict__ b1,
    const float* __restrict__ W2,
    const int* __restrict__ src, const int* __restrict__ dst,
    unsigned* __restrict__ emax, int E)
{
    extern __shared__ uint32_t smu[];
    __shared__ int se[128], de[128];
    const int tid = threadIdx.x;
    const int warp = tid >> 5, lane = tid & 31;
    const int g = lane >> 2, t = lane & 3;
    const int warp_m = warp & 3, warp_n = warp >> 2;
    const int e_base = blockIdx.y * 128;
    const int wm = warp_m * 32, wn = warp_n * 64;
    const int a_row = tid >> 3, a_c4 = (tid & 7) * 4;
    const int b_k2 = tid >> 5, b_c4 = (tid & 31) * 4;

    if (tid < 128) {
        int e = e_base + tid;
        bool ok = (e < E);
        se[tid] = ok ? src[e] : 0;
        de[tid] = ok ? dst[e] : 0;
    }
    __syncthreads();

    float acc[2][8][4];
#pragma unroll
    for (int i = 0; i < 2; i++)
#pragma unroll
        for (int j = 0; j < 8; j++)
#pragma unroll
            for (int c = 0; c < 4; c++) acc[i][j][c] = 0.f;

    float4 bv0[2], bv1[2];

#define EB_LDG(kt)                                                                 \
    {                                                                              \
        _Pragma("unroll")                                                          \
        for (int i = 0; i < 2; i++) {                                              \
            int k2 = b_k2 + i * 8;                                                 \
            bv0[i] = *(const float4*)(W2 + (size_t)((kt) + 2 * k2) * 128 + b_c4);     \
            bv1[i] = *(const float4*)(W2 + (size_t)((kt) + 2 * k2 + 1) * 128 + b_c4); \
        }                                                                          \
    }
#define EB_B_STS(st)                                                               \
    {                                                                              \
        uint32_t* sb = smu + (st) * STAGE_U;                                       \
        _Pragma("unroll")                                                          \
        for (int i = 0; i < 2; i++) STS_B4(sb, b_k2 + i * 8, b_c4, bv0[i], bv1[i]);\
    }
#define EB_A_STS(kt, st)                                                           \
    {                                                                              \
        uint32_t* sb = smu + (st) * STAGE_U;                                       \
        float4 bb = *(const float4*)(b1 + (kt) + a_c4);                            \
        _Pragma("unroll")                                                          \
        for (int i = 0; i < 4; i++) {                                              \
            int row = a_row + i * 32;                                              \
            size_t dof = (size_t)de[row] * 1024, sof = (size_t)se[row] * 1024 + 512; \
            float4 rv = *(const float4*)(PQ + dof + (kt) + a_c4);                  \
            float4 qv = *(const float4*)(PQ + sof + (kt) + a_c4);                  \
            float4 h;                                                              \
            h.x = fmaxf(rv.x + qv.x + bb.x, 0.f);                                  \
            h.y = fmaxf(rv.y + qv.y + bb.y, 0.f);                                  \
            h.z = fmaxf(rv.z + qv.z + bb.z, 0.f);                                  \
            h.w = fmaxf(rv.w + qv.w + bb.w, 0.f);                                  \
            STS_A4(sb, row, a_c4, h);                                              \
        }                                                                          \
    }

    EB_A_STS(0, 0);
    EB_LDG(0);
    int stage = 0;
    for (int kt = 0; kt < 512; kt += 32, stage ^= 1) {
        EB_B_STS(stage);
        __syncthreads();
        if (kt + 32 < 512) EB_LDG(kt + 32);
        const uint32_t* sb = smu + stage * STAGE_U;
        BF_COMPUTE(sb);
        if (kt + 32 < 512) EB_A_STS(kt + 32, stage ^ 1);
    }

#pragma unroll
    for (int mt = 0; mt < 2; mt++) {
        int r0 = wm + mt * 16 + g, r1 = r0 + 8;
        int e0 = e_base + r0, e1 = e_base + r1;
        int d0 = de[r0], d1 = de[r1];
#pragma unroll
        for (int nt = 0; nt < 8; nt++) {
            int c = wn + nt * 8 + 2 * t;
            if (e0 < E) {
                atomicMax(emax + (size_t)d0 * DIMF + c,     fkey(acc[mt][nt][0]));
                atomicMax(emax + (size_t)d0 * DIMF + c + 1, fkey(acc[mt][nt][1]));
            }
            if (e1 < E) {
                atomicMax(emax + (size_t)d1 * DIMF + c,     fkey(acc[mt][nt][2]));
                atomicMax(emax + (size_t)d1 * DIMF + c + 1, fkey(acc[mt][nt][3]));
            }
        }
    }
}

// ---------------- CSR-fused attention kernels (NEW) ----------------
// one warp per dst node: softmax over its contiguous sorted-edge range, no atomics.
__global__ void trans_fused_kernel(
    const float* __restrict__ qkvs, const int* __restrict__ rowptr,
    const int* __restrict__ srcs, float* __restrict__ escore,
    float* __restrict__ out, int n, float scale)
{
    int idx = blockIdx.x * blockDim.x + threadIdx.x;
    int d = idx >> 5, lane = idx & 31;
    if (d >= n) return;
    int beg = rowptr[d], end = rowptr[d + 1];
    if (beg == end) return;
    float4 q = *(const float4*)(qkvs + (size_t)d * 512 + lane * 4);
    float m = -INFINITY;
    for (int e = beg; e < end; e++) {
        int s0 = srcs[e];
        float4 kv = *(const float4*)(qkvs + (size_t)s0 * 512 + 128 + lane * 4);
        float s = q.x * kv.x + q.y * kv.y + q.z * kv.z + q.w * kv.w;
#pragma unroll
        for (int o = 16; o; o >>= 1) s += __shfl_xor_sync(0xffffffffu, s, o);
        s *= scale;
        if (lane == 0) escore[e] = s;
        m = fmaxf(m, s);
    }
    __syncwarp();
    float4 acc = make_float4(0.f, 0.f, 0.f, 0.f);
    float dsum = 0.f;
    for (int e = beg; e < end; e++) {
        float ex = expf(escore[e] - m);
        dsum += ex;
        int s0 = srcs[e];
        float4 vv = *(const float4*)(qkvs + (size_t)s0 * 512 + 256 + lane * 4);
        acc.x += ex * vv.x; acc.y += ex * vv.y;
        acc.z += ex * vv.z; acc.w += ex * vv.w;
    }
    float inv = 1.f / (dsum + 1e-16f);
    float* op = out + (size_t)d * DIMF + lane * 4;
    float4 o = *(float4*)op;
    o.x += acc.x * inv; o.y += acc.y * inv;
    o.z += acc.z * inv; o.w += acc.w * inv;
    *(float4*)op = o;
}

__global__ void gat_fused_kernel(
    const float* __restrict__ ss, const float* __restrict__ sd,
    const float* __restrict__ hs, const int* __restrict__ rowptr,
    const int* __restrict__ srcs, float* __restrict__ escore,
    float* __restrict__ out, int n)
{
    int idx = blockIdx.x * blockDim.x + threadIdx.x;
    int d = idx >> 5, lane = idx & 31;
    if (d >= n) return;
    int beg = rowptr[d], end = rowptr[d + 1];
    if (beg == end) return;
    float sdd = sd[d];
    float m = -INFINITY;
    for (int e = beg + lane; e < end; e += 32) {
        float s = ss[srcs[e]] + sdd;
        s = (s > 0.f) ? s : 0.2f * s;
        escore[e] = s;
        m = fmaxf(m, s);
    }
#pragma unroll
    for (int o = 16; o; o >>= 1) m = fmaxf(m, __shfl_xor_sync(0xffffffffu, m, o));
    __syncwarp();
    float4 acc = make_float4(0.f, 0.f, 0.f, 0.f);
    float dsum = 0.f;
    for (int e = beg; e < end; e++) {
        float ex = expf(escore[e] - m);
        dsum += ex;
        int s0 = srcs[e];
        float4 hv = *(const float4*)(hs + (size_t)s0 * DIMF + lane * 4);
        acc.x += ex * hv.x; acc.y += ex * hv.y;
        acc.z += ex * hv.z; acc.w += ex * hv.w;
    }
    float inv = 1.f / (dsum + 1e-16f);
    float* op = out + (size_t)d * DIMF + lane * 4;
    float4 o = *(float4*)op;
    o.x += acc.x * inv; o.y += acc.y * inv;
    o.z += acc.z * inv; o.w += acc.w * inv;
    *(float4*)op = o;
}

// ---------------- one-time weight prep ----------------
__global__ void concat_trans_kernel(const float* Wq, const float* Wk, const float* Wv,
                                    const float* Ws, const float* bq, const float* bk,
                                    const float* bv, const float* bs,
                                    float* Wcat, float* bcat)
{
    int i = blockIdx.x * blockDim.x + threadIdx.x;
    if (i >= 4 * 128 * 512) return;
    int inst = i >> 16, r = (i >> 9) & 127, j = i & 511;
    int sel = j >> 7, jj = j & 127;
    const float* W = sel == 0 ? Wq : sel == 1 ? Wk : sel == 2 ? Wv : Ws;
    Wcat[i] = W[((size_t)inst * 128 + r) * 128 + jj];
    if (r == 0) {
        const float* bb = sel == 0 ? bq : sel == 1 ? bk : sel == 2 ? bv : bs;
        bcat[inst * 512 + j] = bb[inst * 128 + jj];
    }
}
__global__ void concat_edge_kernel(const float* W1, float* Wcat)
{
    int i = blockIdx.x * blockDim.x + threadIdx.x;
    if (i >= 4 * 128 * 1024) return;
    int inst = i >> 17, r = (i >> 10) & 127, j = i & 1023;
    const float* Wi = W1 + (size_t)inst * 256 * 512;
    if (j < 512) Wcat[i] = Wi[(size_t)r * 512 + j] - Wi[(size_t)(128 + r) * 512 + j];
    else         Wcat[i] = Wi[(size_t)(128 + r) * 512 + (j - 512)];
}
__global__ void wad_kernel(const float* __restrict__ W, const float* __restrict__ ad,
                           float* __restrict__ wad)
{
    int j = threadIdx.x;
    float s = 0.f;
    for (int kk = 0; kk < 128; kk++) s += W[j * 128 + kk] * ad[kk];
    wad[j] = s;
}

// ---------------- counting sort by dst + rowptr ----------------
__global__ void fill_i32_kernel(int* p, int val, int n) {
    int i = blockIdx.x * blockDim.x + threadIdx.x;
    if (i < n) p[i] = val;
}
__global__ void count_kernel(const int* __restrict__ dst, int* __restrict__ hist, int E) {
    int e = blockIdx.x * blockDim.x + threadIdx.x;
    if (e < E) atomicAdd(hist + dst[e], 1);
}
__global__ void scan1_kernel(const int* __restrict__ hist, int* __restrict__ off,
                             int* __restrict__ bsum, int n) {
    __shared__ int sh[SCAN_B];
    int tid = threadIdx.x, i = blockIdx.x * SCAN_B + tid;
    int v = (i < n) ? hist[i] : 0;
    sh[tid] = v; __syncthreads();
    for (int d = 1; d < SCAN_B; d <<= 1) {
        int t2 = (tid >= d) ? sh[tid - d] : 0;
        __syncthreads(); sh[tid] += t2; __syncthreads();
    }
    if (i < n) off[i] = sh[tid] - v;
    if (tid == SCAN_B - 1) bsum[blockIdx.x] = sh[tid];
}
__global__ void scan2_kernel(int* __restrict__ bsum, int nb) {
    __shared__ int sh[SCAN_B];
    int tid = threadIdx.x;
    int v = (tid < nb) ? bsum[tid] : 0;
    sh[tid] = v; __syncthreads();
    for (int d = 1; d < SCAN_B; d <<= 1) {
        int t2 = (tid >= d) ? sh[tid - d] : 0;
        __syncthreads(); sh[tid] += t2; __syncthreads();
    }
    if (tid < nb) bsum[tid] = sh[tid] - v;
}
// produce global start offsets into hist AND save rowptr (if given)
__global__ void scan3_kernel(const int* __restrict__ off, const int* __restrict__ bsum,
                             int* __restrict__ work, int* __restrict__ rowptr,
                             int n, int E) {
    int i = blockIdx.x * blockDim.x + threadIdx.x;
    if (i < n) {
        int v = off[i] + bsum[i / SCAN_B];
        work[i] = v;
        if (rowptr) rowptr[i] = v;
    }
    if (i == 0 && rowptr) rowptr[n] = E;
}
__global__ void scatter_kernel(const int* __restrict__ src, const int* __restrict__ dst,
                               int* __restrict__ work,
                               int* __restrict__ osrc, int* __restrict__ odst, int E) {
    int e = blockIdx.x * blockDim.x + threadIdx.x;
    if (e >= E) return;
    int d = dst[e];
    int pos = atomicAdd(work + d, 1);
    osrc[pos] = src[e];
    if (odst) odst[pos] = d;
}

// ---------------- small glue kernels ----------------
__global__ void fill_u32_kernel(unsigned* p, unsigned val, int n) {
    int i = blockIdx.x * blockDim.x + threadIdx.x;
    if (i < n) p[i] = val;
}
__global__ void copy_skip_kernel(const float* __restrict__ qkvs, float* __restrict__ out, int n) {
    int i = blockIdx.x * blockDim.x + threadIdx.x;
    if (i >= n * 32) return;
    int row = i >> 5, f = (i & 31) * 4;
    *(float4*)(out + (size_t)row * DIMF + f) =
        *(const float4*)(qkvs + (size_t)row * 512 + 384 + f);
}
__global__ void node_dot_kernel(const float* __restrict__ h, const float* __restrict__ avec,
                                float* __restrict__ out, int n)
{
    int idx = blockIdx.x * blockDim.x + threadIdx.x;
    int i = idx >> 5, lane = idx & 31;
    if (i >= n) return;
    float4 hv = *(const float4*)(h + (size_t)i * DIMF + lane * 4);
    float4 av = *(const float4*)(avec + lane * 4);
    float s = hv.x * av.x + hv.y * av.y + hv.z * av.z + hv.w * av.w;
#pragma unroll
    for (int o = 16; o; o >>= 1) s += __shfl_xor_sync(0xffffffffu, s, o);
    if (lane == 0) out[i] = s;
}
__global__ void bias_add_kernel(float* __restrict__ out, const float* __restrict__ b, int n) {
    int i = blockIdx.x * blockDim.x + threadIdx.x;
    if (i >= n * 32) return;
    int f = (i & 31) * 4;
    float4 bv = *(const float4*)(b + f);
    float4 ov = *(float4*)(out + (size_t)i * 4);
    ov.x += bv.x; ov.y += bv.y; ov.z += bv.z; ov.w += bv.w;
    *(float4*)(out + (size_t)i * 4) = ov;
}
__global__ void finalize_max_b2_kernel(const unsigned* __restrict__ emax,
                                       const float* __restrict__ b2,
                                       float* __restrict__ out, int total) {
    int i = blockIdx.x * blockDim.x + threadIdx.x;
    if (i >= total) return;
    float v = fdecode(emax[i]);
    out[i] = isfinite(v) ? v + b2[i & (DIMF - 1)] : 0.f;
}

// ---------------- host orchestration ----------------
static inline int div_up(int a, int b) { return (a + b - 1) / b; }

struct Scratch {
    float *xl, *xp, *la, *pa, *hs, *ss, *sd, *escore, *dsum, *PQ;
    float *WcatT, *bcatT, *WcatE, *wad;
    unsigned *emax;
    int *hist, *work, *bsum;
    int *sll_s, *spp_s, *spp_d, *slp_s, *spl_s;
    int *rp_ll, *rp_lp, *rp_pl;
};

static void sort_graph(const Scratch& S, const int* src, const int* dst, int E, int n,
                       int* osrc, int* odst, int* rowptr)
{
    fill_i32_kernel<<<div_up(n, 256), 256>>>(S.hist, 0, n);
    count_kernel<<<div_up(E, 256), 256>>>(dst, S.hist, E);
    int nb = div_up(n, SCAN_B);
    scan1_kernel<<<nb, SCAN_B>>>(S.hist, S.work, S.bsum, n);
    scan2_kernel<<<1, SCAN_B>>>(S.bsum, nb);
    scan3_kernel<<<div_up(n, 256), 256>>>(S.work, S.bsum, S.hist, rowptr, n, E);
    scatter_kernel<<<div_up(E, 256), 256>>>(src, dst, S.hist, osrc, odst, E);
}

static void sgemm(const float* A, const float* B, const float* bias, float* C,
                  int M, int N, int K) {
    dim3 grid(N / 128, div_up(M, 128));
    bf3_gemm_kernel<<<grid, 256, SMEM_BYTES>>>(A, B, bias, C, M, N, K);
}

static void run_trans(const Scratch& S, const float* x, int n, int inst,
                      const int* rowptr, const int* srcs, float* out)
{
    sgemm(x, S.WcatT + (size_t)inst * 128 * 512, S.bcatT + inst * 512, S.PQ, n, 512, DIMF);
    copy_skip_kernel<<<div_up(n * 32, 256), 256>>>(S.PQ, out, n);
    float scale = 1.f / sqrtf((float)DIMF);
    trans_fused_kernel<<<div_up(n * 32, 256), 256>>>(S.PQ, rowptr, srcs, S.escore,
                                                     out, n, scale);
}

static void run_gat(const Scratch& S, const float* xs, int ns, const float* xd, int nd,
                    const int* rowptr, const int* srcs,
                    const float* W, const float* a_src, const float* a_dst, const float* b,
                    float* out)
{
    sgemm(xs, W, nullptr, S.hs, ns, DIMF, DIMF);
    wad_kernel<<<1, 128>>>(W, a_dst, S.wad);
    node_dot_kernel<<<div_up(ns * 32, 256), 256>>>(S.hs, a_src, S.ss, ns);
    node_dot_kernel<<<div_up(nd * 32, 256), 256>>>(xd, S.wad, S.sd, nd);
    gat_fused_kernel<<<div_up(nd * 32, 256), 256>>>(S.ss, S.sd, S.hs, rowptr, srcs,
                                                    S.escore, out, nd);
    bias_add_kernel<<<div_up(nd * 32, 256), 256>>>(out, b, nd);
}

static void run_edge(const Scratch& S, const float* x, int n, int inst,
                     const int* src, const int* dst, int E,
                     const float* b1, const float* W2, const float* b2, float* out)
{
    sgemm(x, S.WcatE + (size_t)inst * 128 * 1024, nullptr, S.PQ, n, 1024, DIMF);
    fill_u32_kernel<<<div_up(n * DIMF, 256), 256>>>(S.emax, NEG_INF_KEY, n * DIMF);
    dim3 grid(1, div_up(E, 128));
    edge_bf3_kernel<<<grid, 256, SMEM_BYTES>>>(S.PQ, b1, W2, src, dst, S.emax, E);
    finalize_max_b2_kernel<<<div_up(n * DIMF, 256), 256>>>(S.emax, b2, out, n * DIMF);
}

extern "C" void kernel_launch(void* const* d_in, const int* in_sizes, int n_in,
                              void* d_out, int out_size)
{
    const float* x_lego  = (const float*)d_in[0];
    const float* x_point = (const float*)d_in[1];
    const float* tWq = (const float*)d_in[2];
    const float* tbq = (const float*)d_in[3];
    const float* tWk = (const float*)d_in[4];
    const float* tbk = (const float*)d_in[5];
    const float* tWv = (const float*)d_in[6];
    const float* tbv = (const float*)d_in[7];
    const float* tWs = (const float*)d_in[8];
    const float* tbs = (const float*)d_in[9];
    const float* eW1 = (const float*)d_in[10];
    const float* eb1 = (const float*)d_in[11];
    const float* eW2 = (const float*)d_in[12];
    const float* eb2 = (const float*)d_in[13];
    const float* gW  = (const float*)d_in[14];
    const float* gAs = (const float*)d_in[15];
    const float* gAd = (const float*)d_in[16];
    const float* gb  = (const float*)d_in[17];
    const int* ll_src = (const int*)d_in[18];
    const int* ll_dst = (const int*)d_in[19];
    const int* pp_src = (const int*)d_in[20];
    const int* pp_dst = (const int*)d_in[21];
    const int* lp_src = (const int*)d_in[22];
    const int* lp_dst = (const int*)d_in[23];
    const int* pl_src = (const int*)d_in[24];
    const int* pl_dst = (const int*)d_in[25];

    cudaFuncSetAttribute(bf3_gemm_kernel, cudaFuncAttributeMaxDynamicSharedMemorySize,
                         SMEM_BYTES);
    cudaFuncSetAttribute(edge_bf3_kernel, cudaFuncAttributeMaxDynamicSharedMemorySize,
                         SMEM_BYTES);

    Scratch S;
    cudaGetSymbolAddress((void**)&S.xl, g_xl);
    cudaGetSymbolAddress((void**)&S.xp, g_xp);
    cudaGetSymbolAddress((void**)&S.la, g_la);
    cudaGetSymbolAddress((void**)&S.pa, g_pa);
    cudaGetSymbolAddress((void**)&S.hs, g_hs);
    cudaGetSymbolAddress((void**)&S.ss, g_ss);
    cudaGetSymbolAddress((void**)&S.sd, g_sd);
    cudaGetSymbolAddress((void**)&S.escore, g_escore);
    cudaGetSymbolAddress((void**)&S.dsum, g_dsum);
    cudaGetSymbolAddress((void**)&S.PQ, g_PQ);
    cudaGetSymbolAddress((void**)&S.emax, g_emax);
    cudaGetSymbolAddress((void**)&S.WcatT, g_WcatT);
    cudaGetSymbolAddress((void**)&S.bcatT, g_bcatT);
    cudaGetSymbolAddress((void**)&S.WcatE, g_WcatE);
    cudaGetSymbolAddress((void**)&S.wad, g_wad);
    cudaGetSymbolAddress((void**)&S.hist, g_hist);
    cudaGetSymbolAddress((void**)&S.work, g_work);
    cudaGetSymbolAddress((void**)&S.bsum, g_bsum);
    cudaGetSymbolAddress((void**)&S.sll_s, g_sll_s);
    cudaGetSymbolAddress((void**)&S.spp_s, g_spp_s);
    cudaGetSymbolAddress((void**)&S.spp_d, g_spp_d);
    cudaGetSymbolAddress((void**)&S.slp_s, g_slp_s);
    cudaGetSymbolAddress((void**)&S.spl_s, g_spl_s);
    cudaGetSymbolAddress((void**)&S.rp_ll, g_rp_ll);
    cudaGetSymbolAddress((void**)&S.rp_lp, g_rp_lp);
    cudaGetSymbolAddress((void**)&S.rp_pl, g_rp_pl);

    cudaMemcpyAsync(S.xl, x_lego,  (size_t)N_LEGO * DIMF * sizeof(float),  cudaMemcpyDeviceToDevice);
    cudaMemcpyAsync(S.xp, x_point, (size_t)N_POINT * DIMF * sizeof(float), cudaMemcpyDeviceToDevice);

    concat_trans_kernel<<<div_up(4 * 128 * 512, 256), 256>>>(tWq, tWk, tWv, tWs,
                                                             tbq, tbk, tbv, tbs,
                                                             S.WcatT, S.bcatT);
    concat_edge_kernel<<<div_up(4 * 128 * 1024, 256), 256>>>(eW1, S.WcatE);

    // sort by dst once; keep CSR rowptrs for attention relations
    sort_graph(S, ll_src, ll_dst, NE_LL, N_LEGO,  S.sll_s, nullptr, S.rp_ll);
    sort_graph(S, pp_src, pp_dst, NE_PP, N_POINT, S.spp_s, S.spp_d, nullptr);
    sort_graph(S, lp_src, lp_dst, NE_LP, N_POINT, S.slp_s, nullptr, S.rp_lp);
    sort_graph(S, pl_src, pl_dst, NE_PL, N_LEGO,  S.spl_s, nullptr, S.rp_pl);

    for (int layer = 0; layer < 2; layer++) {
        int iA = 2 * layer, iB = 2 * layer + 1;
        int i_lp = 2 * layer, i_pl = 2 * layer + 1;

        run_trans(S, S.xl, N_LEGO, iA, S.rp_ll, S.sll_s, S.la);
        run_gat(S, S.xp, N_POINT, S.xl, N_LEGO, S.rp_pl, S.spl_s,
                gW + i_pl * DIMF * DIMF, gAs + i_pl * DIMF, gAd + i_pl * DIMF, gb + i_pl * DIMF,
                S.la);

        run_edge(S, S.xp, N_POINT, iA, S.spp_s, S.spp_d, NE_PP,
                 eb1 + iA * 512, eW2 + (size_t)iA * 512 * DIMF, eb2 + iA * DIMF, S.pa);
        run_gat(S, S.xl, N_LEGO, S.xp, N_POINT, S.rp_lp, S.slp_s,
                gW + i_lp * DIMF * DIMF, gAs + i_lp * DIMF, gAd + i_lp * DIMF, gb + i_lp * DIMF,
                S.pa);

        run_trans(S, S.la, N_LEGO, iB, S.rp_ll, S.sll_s, S.xl);
        run_edge(S, S.pa, N_POINT, iB, S.spp_s, S.spp_d, NE_PP,
                 eb1 + iB * 512, eW2 + (size_t)iB * 512 * DIMF, eb2 + iB * DIMF, S.xp);
    }

    float* out = (float*)d_out;
    cudaMemcpyAsync(out, S.xl, (size_t)N_LEGO * DIMF * sizeof(float), cudaMemcpyDeviceToDevice);
    cudaMemcpyAsync(out + (size_t)N_LEGO * DIMF, S.xp, (size_t)N_POINT * DIMF * sizeof(float),
                    cudaMemcpyDeviceToDevice);
}